// round 6
// baseline (speedup 1.0000x reference)
#include <cuda_runtime.h>
#include <math.h>
#include <stdint.h>

// ---------------- problem constants ----------------
#define NE 40000
#define NN 10000
#define NFULL 25          // (LMAX+1)^2
#define NM 19             // NUM_M
#define MSG1_W 2432       // 19*128
#define H1_W 1216         // 19*64
#define RAD_W 1536
#define OUT_ELEMS (NN * NFULL * 64)

// ---------------- static scratch (allowed: __device__ globals) ----------------
static __device__ float g_t64a[(size_t)NE * 64];
static __device__ float g_t64b[(size_t)NE * 64];
static __device__ float g_rad [(size_t)NE * RAD_W];
static __device__ float g_msg1[(size_t)NE * MSG1_W];
static __device__ float g_t576[(size_t)NE * 576];
static __device__ float g_y0  [(size_t)NE * 512];
static __device__ float g_y1  [(size_t)NE * 512];
static __device__ float g_z0  [(size_t)NE * 384];
static __device__ float g_z1  [(size_t)NE * 384];
static __device__ float g_h1  [(size_t)NE * H1_W];
static __device__ float g_t320[(size_t)NE * 320];
static __device__ float g_msg2[(size_t)NE * H1_W];

// ---------------- helpers ----------------
__device__ __forceinline__ float sigmoidf_(float x) { return 1.0f / (1.0f + expf(-x)); }
__device__ __forceinline__ float siluf_(float x)    { return x / (1.0f + expf(-x)); }

// ---------------- zero fill ----------------
__global__ void zero_kernel(float* p, int n) {
    int i = blockIdx.x * blockDim.x + threadIdx.x;
    if (i < n) p[i] = 0.0f;
}

// ---------------- generic tiled GEMM: C[M=NE,N] = A[M,K](lda) @ W[K,N] (+bias) ----------------
// Requires: M % 64 == 0, N % 64 == 0, K % 16 == 0, lda % 4 == 0, base ptrs 16B-aligned.
__global__ void __launch_bounds__(256) gemm64(
    const float* __restrict__ A, int lda,
    const float* __restrict__ W, int N, int K,
    const float* __restrict__ bias,
    float* __restrict__ C, int ldc)
{
    __shared__ __align__(16) float As[16][68];   // [k][m], padded
    __shared__ __align__(16) float Bs[16][64];   // [k][n]

    int tid = threadIdx.x;
    int tx = tid & 15;          // n-tile coord (4 cols each)
    int ty = tid >> 4;          // m-tile coord (4 rows each)
    int m0 = blockIdx.y * 64;
    int n0 = blockIdx.x * 64;

    // A tile loader: thread -> row ar, float4 at col ac
    int ar = tid >> 2;            // 0..63
    int ac = (tid & 3) * 4;       // 0,4,8,12
    // B tile loader: thread -> row wr, float4 at col wc
    int wr = tid >> 4;            // 0..15
    int wc = (tid & 15) * 4;      // 0..60

    const float* Ap = A + (size_t)(m0 + ar) * lda + ac;

    float acc[4][4];
#pragma unroll
    for (int i = 0; i < 4; i++)
#pragma unroll
        for (int j = 0; j < 4; j++) acc[i][j] = 0.0f;

    for (int k0 = 0; k0 < K; k0 += 16) {
        float4 av = *(const float4*)(Ap + k0);
        float4 bv = *(const float4*)(W + (size_t)(k0 + wr) * N + n0 + wc);
        As[ac + 0][ar] = av.x;
        As[ac + 1][ar] = av.y;
        As[ac + 2][ar] = av.z;
        As[ac + 3][ar] = av.w;
        *(float4*)&Bs[wr][wc] = bv;
        __syncthreads();
#pragma unroll
        for (int kk = 0; kk < 16; kk++) {
            float4 a = *(const float4*)&As[kk][ty * 4];
            float4 b = *(const float4*)&Bs[kk][tx * 4];
            float av_[4] = {a.x, a.y, a.z, a.w};
            float bv_[4] = {b.x, b.y, b.z, b.w};
#pragma unroll
            for (int i = 0; i < 4; i++)
#pragma unroll
                for (int j = 0; j < 4; j++)
                    acc[i][j] += av_[i] * bv_[j];
        }
        __syncthreads();
    }

    float bb[4] = {0.f, 0.f, 0.f, 0.f};
    if (bias) {
#pragma unroll
        for (int j = 0; j < 4; j++) bb[j] = bias[n0 + tx * 4 + j];
    }
#pragma unroll
    for (int i = 0; i < 4; i++) {
        float* Cp = C + (size_t)(m0 + ty * 4 + i) * ldc + n0 + tx * 4;
#pragma unroll
        for (int j = 0; j < 4; j++) Cp[j] = acc[i][j] + bb[j];
    }
}

// ---------------- LayerNorm + SiLU over 64 channels, in-place ----------------
__global__ void lnsilu_kernel(float* __restrict__ h,
                              const float* __restrict__ g,
                              const float* __restrict__ b)
{
    int e = blockIdx.x;
    int t = threadIdx.x;   // 64 threads
    float v = h[(size_t)e * 64 + t];

    __shared__ float red[4];
    float s = v;
#pragma unroll
    for (int o = 16; o > 0; o >>= 1) s += __shfl_xor_sync(0xffffffffu, s, o);
    if ((t & 31) == 0) red[t >> 5] = s;
    __syncthreads();
    float mu = (red[0] + red[1]) * (1.0f / 64.0f);

    float d = v - mu;
    float s2 = d * d;
#pragma unroll
    for (int o = 16; o > 0; o >>= 1) s2 += __shfl_xor_sync(0xffffffffu, s2, o);
    if ((t & 31) == 0) red[2 + (t >> 5)] = s2;
    __syncthreads();
    float var = (red[2] + red[3]) * (1.0f / 64.0f);

    float y = d * rsqrtf(var + 1e-5f) * g[t] + b[t];
    h[(size_t)e * 64 + t] = siluf_(y);
}

// ---------------- wigner forward: msg1[e] = (wigner[e] @ concat(x[src],x[dst])) * radscale ----------------
__global__ void __launch_bounds__(256) wig_fwd_kernel(
    const float* __restrict__ x,
    const int* __restrict__ edge_index,
    const float* __restrict__ wigner,
    const float* __restrict__ rad,
    float* __restrict__ msg1)
{
    int e = blockIdx.x;
    int tid = threadIdx.x;
    __shared__ float sw[NM * NFULL];      // 475
    __shared__ float sx[NFULL * 128];     // 3200

    int src = edge_index[e];
    int dst = edge_index[NE + e];

    const float* wp = wigner + (size_t)e * (NM * NFULL);
    for (int i = tid; i < NM * NFULL; i += 256) sw[i] = wp[i];

    const float* xs = x + (size_t)src * (NFULL * 64);
    const float* xd = x + (size_t)dst * (NFULL * 64);
    for (int i = tid; i < NFULL * 64; i += 256) {
        int k = i >> 6, c = i & 63;
        sx[k * 128 + c]       = xs[i];
        sx[k * 128 + 64 + c]  = xd[i];
    }
    __syncthreads();

    float* mp = msg1 + (size_t)e * MSG1_W;
    const float* rp = rad + (size_t)e * RAD_W;
    for (int o = tid; o < MSG1_W; o += 256) {
        int r = o >> 7, f = o & 127;
        float s = 0.0f;
        const float* wrow = &sw[r * NFULL];
#pragma unroll
        for (int k = 0; k < NFULL; k++) s += wrow[k] * sx[k * 128 + f];
        int sidx;
        if (r < 5)        sidx = r * 128 + f;
        else if (r < 13)  sidx = 640  + ((r - 5) & 3) * 128 + f;
        else              sidx = 1152 + ((r - 13) % 3) * 128 + f;
        mp[o] = s * rp[sidx];
    }
}

// ---------------- assemble conv1 output + gate -> g_h1 (E, 1216) ----------------
__global__ void __launch_bounds__(256) assemble1_kernel(
    const float* __restrict__ t576,
    const float* __restrict__ y0, const float* __restrict__ y1,
    const float* __restrict__ z0, const float* __restrict__ z1,
    float* __restrict__ h1)
{
    int e = blockIdx.x;
    int tid = threadIdx.x;
    const float* T  = t576 + (size_t)e * 576;
    const float* Y0 = y0 + (size_t)e * 512;
    const float* Y1 = y1 + (size_t)e * 512;
    const float* Z0 = z0 + (size_t)e * 384;
    const float* Z1 = z1 + (size_t)e * 384;
    float* H = h1 + (size_t)e * H1_W;

    for (int o = tid; o < H1_W; o += 256) {
        int r = o >> 6, c = o & 63;
        float v;
        if (r < 5)       v = T[r * 64 + c];
        else if (r < 9)  { int j = r - 5;  v = Y0[j * 64 + c] - Y1[256 + j * 64 + c]; }
        else if (r < 13) { int j = r - 9;  v = Y1[j * 64 + c] + Y0[256 + j * 64 + c]; }
        else if (r < 16) { int j = r - 13; v = Z0[j * 64 + c] - Z1[192 + j * 64 + c]; }
        else             { int j = r - 16; v = Z1[j * 64 + c] + Z0[192 + j * 64 + c]; }

        if (r == 0) {
            v = siluf_(v);
        } else {
            int lp;
            if (r < 5)       lp = r - 1;
            else if (r < 9)  lp = r - 5;
            else if (r < 13) lp = r - 9;
            else if (r < 16) lp = r - 12;
            else             lp = r - 15;
            v *= sigmoidf_(T[320 + lp * 64 + c]);
        }
        H[o] = v;
    }
}

// ---------------- assemble conv2 output * envelope -> g_msg2 ----------------
__global__ void __launch_bounds__(256) assemble2_kernel(
    const float* __restrict__ t320,
    const float* __restrict__ y0, const float* __restrict__ y1,
    const float* __restrict__ z0, const float* __restrict__ z1,
    const float* __restrict__ edge_distance,
    float* __restrict__ msg2)
{
    int e = blockIdx.x;
    int tid = threadIdx.x;
    float d = edge_distance[e] * (1.0f / 6.0f);
    float d2 = d * d;
    float d5 = d2 * d2 * d;
    float env = (d < 1.0f) ? (1.0f - 21.0f * d5 + 35.0f * d5 * d - 15.0f * d5 * d2) : 0.0f;

    const float* T  = t320 + (size_t)e * 320;
    const float* Y0 = y0 + (size_t)e * 512;
    const float* Y1 = y1 + (size_t)e * 512;
    const float* Z0 = z0 + (size_t)e * 384;
    const float* Z1 = z1 + (size_t)e * 384;
    float* M = msg2 + (size_t)e * H1_W;

    for (int o = tid; o < H1_W; o += 256) {
        int r = o >> 6, c = o & 63;
        float v;
        if (r < 5)       v = T[r * 64 + c];
        else if (r < 9)  { int j = r - 5;  v = Y0[j * 64 + c] - Y1[256 + j * 64 + c]; }
        else if (r < 13) { int j = r - 9;  v = Y1[j * 64 + c] + Y0[256 + j * 64 + c]; }
        else if (r < 16) { int j = r - 13; v = Z0[j * 64 + c] - Z1[192 + j * 64 + c]; }
        else             { int j = r - 16; v = Z1[j * 64 + c] + Z0[192 + j * 64 + c]; }
        M[o] = v * env;
    }
}

// ---------------- wigner inverse + scatter-add ----------------
__global__ void __launch_bounds__(256) wig_inv_kernel(
    const float* __restrict__ wigner_inv,
    const float* __restrict__ msg2,
    const int* __restrict__ edge_index,
    float* __restrict__ out)
{
    int e = blockIdx.x;
    int tid = threadIdx.x;
    __shared__ float sw[NFULL * NM];   // 475
    __shared__ float sm[NM * 64];      // 1216

    const float* wp = wigner_inv + (size_t)e * (NFULL * NM);
    for (int i = tid; i < NFULL * NM; i += 256) sw[i] = wp[i];
    const float* mp = msg2 + (size_t)e * H1_W;
    for (int i = tid; i < H1_W; i += 256) sm[i] = mp[i];
    __syncthreads();

    int dst = edge_index[NE + e];
    float* op = out + (size_t)dst * (NFULL * 64);
    for (int o = tid; o < NFULL * 64; o += 256) {
        int j = o >> 6, c = o & 63;
        float s = 0.0f;
        const float* wrow = &sw[j * NM];
#pragma unroll
        for (int r = 0; r < NM; r++) s += wrow[r] * sm[r * 64 + c];
        atomicAdd(&op[o], s);
    }
}

// ---------------- host side ----------------
static float* symaddr(const void* sym) {
    void* p = nullptr;
    cudaGetSymbolAddress(&p, sym);
    return (float*)p;
}

static void gemm(const float* A, int lda, const float* W, int N, int K,
                 const float* bias, float* C, int ldc) {
    dim3 grid(N / 64, NE / 64);
    gemm64<<<grid, 256>>>(A, lda, W, N, K, bias, C, ldc);
}

extern "C" void kernel_launch(void* const* d_in, const int* in_sizes, int n_in,
                              void* d_out, int out_size)
{
    const float* x             = (const float*)d_in[0];
    const float* x_edge        = (const float*)d_in[1];
    const float* edge_distance = (const float*)d_in[2];
    const int*   edge_index    = (const int*)  d_in[3];
    const float* wigner        = (const float*)d_in[4];
    const float* wigner_inv    = (const float*)d_in[5];
    const float* rad_w0        = (const float*)d_in[6];
    const float* rad_b0        = (const float*)d_in[7];
    const float* rad_ln0_g     = (const float*)d_in[8];
    const float* rad_ln0_b     = (const float*)d_in[9];
    const float* rad_w1        = (const float*)d_in[10];
    const float* rad_b1        = (const float*)d_in[11];
    const float* rad_ln1_g     = (const float*)d_in[12];
    const float* rad_ln1_b     = (const float*)d_in[13];
    const float* rad_w2        = (const float*)d_in[14];
    const float* rad_b2        = (const float*)d_in[15];
    const float* c1_fc0_w      = (const float*)d_in[16];
    const float* c1_fc0_b      = (const float*)d_in[17];
    const float* c1_m1_w       = (const float*)d_in[18];
    const float* c1_m2_w       = (const float*)d_in[19];
    const float* c2_fc0_w      = (const float*)d_in[20];
    const float* c2_fc0_b      = (const float*)d_in[21];
    const float* c2_m1_w       = (const float*)d_in[22];
    const float* c2_m2_w       = (const float*)d_in[23];
    float* out = (float*)d_out;

    float* p_t64a = symaddr(g_t64a);
    float* p_t64b = symaddr(g_t64b);
    float* p_rad  = symaddr(g_rad);
    float* p_msg1 = symaddr(g_msg1);
    float* p_t576 = symaddr(g_t576);
    float* p_y0   = symaddr(g_y0);
    float* p_y1   = symaddr(g_y1);
    float* p_z0   = symaddr(g_z0);
    float* p_z1   = symaddr(g_z1);
    float* p_h1   = symaddr(g_h1);
    float* p_t320 = symaddr(g_t320);
    float* p_msg2 = symaddr(g_msg2);

    // 0. zero output (poisoned by harness)
    zero_kernel<<<(OUT_ELEMS + 255) / 256, 256>>>(out, OUT_ELEMS);

    // 1. radial MLP
    gemm(x_edge, 128, rad_w0, 64, 128, rad_b0, p_t64a, 64);
    lnsilu_kernel<<<NE, 64>>>(p_t64a, rad_ln0_g, rad_ln0_b);
    gemm(p_t64a, 64, rad_w1, 64, 64, rad_b1, p_t64b, 64);
    lnsilu_kernel<<<NE, 64>>>(p_t64b, rad_ln1_g, rad_ln1_b);
    gemm(p_t64b, 64, rad_w2, RAD_W, 64, rad_b2, p_rad, RAD_W);

    // 2. gather + wigner rotate + radial prescale
    wig_fwd_kernel<<<NE, 256>>>(x, edge_index, wigner, p_rad, p_msg1);

    // 3. conv1 GEMMs
    gemm(p_msg1 + 0,    MSG1_W, c1_fc0_w, 576, 640, c1_fc0_b, p_t576, 576);
    gemm(p_msg1 + 640,  MSG1_W, c1_m1_w,  512, 512, nullptr,  p_y0,   512);
    gemm(p_msg1 + 1152, MSG1_W, c1_m1_w,  512, 512, nullptr,  p_y1,   512);
    gemm(p_msg1 + 1664, MSG1_W, c1_m2_w,  384, 384, nullptr,  p_z0,   384);
    gemm(p_msg1 + 2048, MSG1_W, c1_m2_w,  384, 384, nullptr,  p_z1,   384);

    // 4. SO2 combine + gate
    assemble1_kernel<<<NE, 256>>>(p_t576, p_y0, p_y1, p_z0, p_z1, p_h1);

    // 5. conv2 GEMMs
    gemm(p_h1 + 0,    H1_W, c2_fc0_w, 320, 320, c2_fc0_b, p_t320, 320);
    gemm(p_h1 + 320,  H1_W, c2_m1_w,  512, 256, nullptr,  p_y0,   512);
    gemm(p_h1 + 576,  H1_W, c2_m1_w,  512, 256, nullptr,  p_y1,   512);
    gemm(p_h1 + 832,  H1_W, c2_m2_w,  384, 192, nullptr,  p_z0,   384);
    gemm(p_h1 + 1024, H1_W, c2_m2_w,  384, 192, nullptr,  p_z1,   384);

    // 6. SO2 combine + envelope
    assemble2_kernel<<<NE, 256>>>(p_t320, p_y0, p_y1, p_z0, p_z1, edge_distance, p_msg2);

    // 7. inverse wigner + scatter-add
    wig_inv_kernel<<<NE, 256>>>(wigner_inv, p_msg2, edge_index, out);
}